// round 7
// baseline (speedup 1.0000x reference)
#include <cuda_runtime.h>
#include <cuda_bf16.h>
#include <cuda_fp8.h>
#include <math.h>
#include <stdint.h>

// ============================================================================
// Problem constants (fixed by reference setup_inputs)
// ============================================================================
#define NTEST  8192
#define NTRAIN 8192
#define DIM    256

#define TM 128
#define TN 128
#define N_ROW_TILES (NTEST / TM)                // 64
#define TOT_TILES   (N_ROW_TILES * (NTRAIN/TN)) // 4096
#define GRID 296                                 // 2 CTAs/SM x 148 = one wave

// Scratch (__device__ globals: allocation-free rule)
__device__ float g_XX[NTEST];
__device__ float g_YY[NTRAIN];
__device__ int   g_sat = 0;   // sticky: any |x|>440 -> exact path (deterministic per input)
__device__ __align__(128) uint8_t g_A8[NTEST  * DIM];
__device__ __align__(128) uint8_t g_B8[NTRAIN * DIM];

// ============================================================================
// helpers
// ============================================================================
__device__ __forceinline__ uint32_t smem_u32(const void* p) {
    uint32_t a;
    asm("{ .reg .u64 t; cvta.to.shared.u64 t, %1; cvt.u32.u64 %0, t; }" : "=r"(a) : "l"(p));
    return a;
}
__device__ __forceinline__ void cp16(uint32_t dst, const void* src) {
    asm volatile("cp.async.cg.shared.global [%0], [%1], 16;" :: "r"(dst), "l"(src));
}
#define CP_COMMIT() asm volatile("cp.async.commit_group;" ::: "memory")

__device__ __forceinline__ void ldsm_x4(uint32_t (&r)[4], uint32_t addr) {
    asm volatile("ldmatrix.sync.aligned.m8n8.x4.shared.b16 {%0,%1,%2,%3}, [%4];"
                 : "=r"(r[0]), "=r"(r[1]), "=r"(r[2]), "=r"(r[3]) : "r"(addr));
}
__device__ __forceinline__ void mma_fp8(float (&c)[4], const uint32_t (&a)[4],
                                        uint32_t b0, uint32_t b1) {
    asm volatile(
        "mma.sync.aligned.m16n8k32.row.col.f32.e4m3.e4m3.f32 "
        "{%0,%1,%2,%3}, {%4,%5,%6,%7}, {%8,%9}, {%0,%1,%2,%3};"
        : "+f"(c[0]), "+f"(c[1]), "+f"(c[2]), "+f"(c[3])
        : "r"(a[0]), "r"(a[1]), "r"(a[2]), "r"(a[3]), "r"(b0), "r"(b1));
}

// ============================================================================
// Kernel 1: norms + e4m3 conversion + saturation flag + out[] init
// ============================================================================
__global__ void gp_precompute_kernel(const float* __restrict__ Xtest,
                                     const float* __restrict__ Xtrain,
                                     const float* __restrict__ mean_const,
                                     float* __restrict__ out)
{
    const int warp = threadIdx.x >> 5;
    const int lane = threadIdx.x & 31;
    int row = blockIdx.x * 8 + warp;
    if (row >= NTEST + NTRAIN) return;

    const float* X; float* dst; uint8_t* bdst; bool isTest;
    if (row < NTEST) { X = Xtest;  dst = g_XX; bdst = g_A8; isTest = true; }
    else { row -= NTEST; X = Xtrain; dst = g_YY; bdst = g_B8; isTest = false; }

    // lane handles 8 consecutive floats
    const float4* p4 = (const float4*)(X + (size_t)row * DIM) + 2 * lane;
    const float4 v0 = p4[0], v1 = p4[1];
    float v[8] = {v0.x, v0.y, v0.z, v0.w, v1.x, v1.y, v1.z, v1.w};

    float s = 0.f, mx = 0.f;
    uint8_t b8[8];
    #pragma unroll
    for (int j = 0; j < 8; j++) {
        s  = fmaf(v[j], v[j], s);
        mx = fmaxf(mx, fabsf(v[j]));
        b8[j] = (uint8_t)__nv_cvt_float_to_fp8(v[j], __NV_SATFINITE, __NV_E4M3);
    }
    uint2 packed;
    packed.x = (uint32_t)b8[0] | ((uint32_t)b8[1] << 8) | ((uint32_t)b8[2] << 16) | ((uint32_t)b8[3] << 24);
    packed.y = (uint32_t)b8[4] | ((uint32_t)b8[5] << 8) | ((uint32_t)b8[6] << 16) | ((uint32_t)b8[7] << 24);
    ((uint2*)(bdst + (size_t)row * DIM))[lane] = packed;

    #pragma unroll
    for (int o = 16; o > 0; o >>= 1) {
        s  += __shfl_xor_sync(0xffffffffu, s, o);
        mx = fmaxf(mx, __shfl_xor_sync(0xffffffffu, mx, o));
    }
    if (lane == 0) {
        dst[row] = s;
        if (mx > 440.f) atomicOr(&g_sat, 1);   // e4m3 saturation -> force exact path
        if (isTest) out[row] = *mean_const;
    }
}

// ============================================================================
// Kernel 2: FP8 HMMA screening GEMM + underflow-exact epilogue.
// 2 CTAs/SM (smem 97KB/CTA). Screen: lb = s - 0.1875*q - 0.25 (rigorous e4m3
// error bound); elements failing the screen get exact fp32 recompute + expf.
// ============================================================================
__global__ __launch_bounds__(256, 2)
void gp_hmma_kernel(const float* __restrict__ Xtest,
                    const float* __restrict__ Xtrain,
                    const float* __restrict__ mu,
                    const float* __restrict__ ls_p,
                    const float* __restrict__ sv_p,
                    float* __restrict__ out)
{
    extern __shared__ char dsm[];
    __shared__ float s_yy[2][TN];
    __shared__ float s_mu[2][TN];

    const int tid  = threadIdx.x;
    const int wid  = tid >> 5;
    const int lane = tid & 31;
    const int bid  = blockIdx.x;

    const uint32_t dsm_u = smem_u32(dsm);
    const uint32_t uA  = (dsm_u + 1023u) & ~1023u;
    const uint32_t uB0 = uA  + 32768u;
    const uint32_t uB1 = uB0 + 32768u;

    const int warp_m = (wid & 3) * 32;   // 4 warps along M
    const int warp_n = (wid >> 2) * 64;  // 2 warps along N

    // ldmatrix lane geometry (byte-identical to bf16 version; 16B chunks)
    const int rA0   = warp_m + (lane & 15);
    const uint32_t swA = (uint32_t)((rA0 & 7) << 4);
    const uint32_t aKl = (uint32_t)((lane >> 4) << 4);
    const int rB0   = warp_n + (lane & 7) + ((lane >> 4) << 3);
    const uint32_t swB = (uint32_t)((rB0 & 7) << 4);
    const uint32_t bKl = (uint32_t)(((lane >> 3) & 1) << 4);

    uint32_t rbaseA[2], rbaseB[4];
    #pragma unroll
    for (int mf = 0; mf < 2; mf++) rbaseA[mf] = uA + (uint32_t)((rA0 + 16 * mf) << 7);
    #pragma unroll
    for (int np = 0; np < 4; np++) rbaseB[np] = (uint32_t)((rB0 + 16 * np) << 7);

    const float l      = *ls_p;
    const float negInv = -0.5f / (l * l);
    const float sCut   = 211.0f * l * l;   // expf == exactly 0 above this
    const float sv     = *sv_p;
    const bool  force  = (g_sat != 0);     // saturation anywhere -> exact everywhere

    const int t_begin = (int)(((long long)bid     * TOT_TILES) / GRID);
    const int t_end   = (int)(((long long)(bid+1) * TOT_TILES) / GRID);

    // tile fill: 128 rows x 256B, 2 sub-tiles of 128x128B, swizzled
    auto fill_tile = [&](uint32_t ubase, const uint8_t* src) {
        #pragma unroll
        for (int q0 = 0; q0 < 8; q0++) {
            const int q = q0 * 256 + tid;
            const int r = q >> 4, c16 = q & 15;
            const uint32_t dst = ubase + (uint32_t)(((c16 >> 3) << 14) + (r << 7)
                                + (((c16 & 7) << 4) ^ ((r & 7) << 4)));
            cp16(dst, src + r * DIM + c16 * 16);
        }
    };

    int i = t_begin;
    while (i < t_end) {
        const int rt      = i >> 6;
        const int seg_end = min(t_end, (rt + 1) << 6);
        const int n       = seg_end - i;
        const int row0    = rt * TM;

        fill_tile(uA, g_A8 + (size_t)row0 * DIM);
        CP_COMMIT();
        {
            const int n0 = (i & 63) * TN;
            fill_tile(uB0, g_B8 + (size_t)n0 * DIM);
            CP_COMMIT();
            if (tid < TN) s_yy[0][tid] = g_YY[n0 + tid];
            else          s_mu[0][tid - TN] = mu[n0 + tid - TN];
        }

        float xv[4];
        #pragma unroll
        for (int j = 0; j < 4; j++) xv[j] = g_XX[row0 + warp_m + (lane >> 2) + 8 * j];
        float xmin = fminf(fminf(xv[0], xv[1]), fminf(xv[2], xv[3]));
        #pragma unroll
        for (int o = 16; o > 0; o >>= 1) xmin = fminf(xmin, __shfl_xor_sync(0xffffffffu, xmin, o));

        for (int tl = 0; tl < n; tl++) {
            const int buf = tl & 1;
            const uint32_t uB = buf ? uB1 : uB0;

            const bool more = (tl + 1 < n);
            if (more) {
                const int n0n = ((i + tl + 1) & 63) * TN;
                fill_tile(buf ? uB0 : uB1, g_B8 + (size_t)n0n * DIM);
                CP_COMMIT();
                if (tid < TN) s_yy[buf ^ 1][tid] = g_YY[n0n + tid];
                else          s_mu[buf ^ 1][tid - TN] = mu[n0n + tid - TN];
            }
            if (more) asm volatile("cp.async.wait_group 1;" ::: "memory");
            else      asm volatile("cp.async.wait_group 0;" ::: "memory");
            __syncthreads();

            // ---- MMA: 128x128x256 via fp8 m16n8k32, 8 k-steps ----
            float acc[2][8][4];
            #pragma unroll
            for (int mf = 0; mf < 2; mf++)
                #pragma unroll
                for (int nf = 0; nf < 8; nf++)
                    #pragma unroll
                    for (int e = 0; e < 4; e++) acc[mf][nf][e] = 0.f;

            #pragma unroll
            for (int kk = 0; kk < 8; kk++) {
                const uint32_t kcOff = (uint32_t)((kk >> 2) << 14);
                const uint32_t oA = kcOff + ((((uint32_t)(kk & 3) << 5) + aKl) ^ swA);
                const uint32_t oB = kcOff + ((((uint32_t)(kk & 3) << 5) + bKl) ^ swB);

                uint32_t a[2][4], b[4][4];
                #pragma unroll
                for (int mf = 0; mf < 2; mf++) ldsm_x4(a[mf], rbaseA[mf] + oA);
                #pragma unroll
                for (int np = 0; np < 4; np++) ldsm_x4(b[np], uB + rbaseB[np] + oB);

                #pragma unroll
                for (int mf = 0; mf < 2; mf++)
                    #pragma unroll
                    for (int nf = 0; nf < 8; nf++)
                        mma_fp8(acc[mf][nf], a[mf],
                                b[nf >> 1][(nf & 1) * 2], b[nf >> 1][(nf & 1) * 2 + 1]);
            }

            // ---- epilogue: warp-level rigorous screen ----
            float cmax = -3.4e38f;
            #pragma unroll
            for (int mf = 0; mf < 2; mf++)
                #pragma unroll
                for (int nf = 0; nf < 8; nf++)
                    #pragma unroll
                    for (int e = 0; e < 4; e++) cmax = fmaxf(cmax, acc[mf][nf][e]);
            #pragma unroll
            for (int o = 16; o > 0; o >>= 1) cmax = fmaxf(cmax, __shfl_xor_sync(0xffffffffu, cmax, o));

            float ymin = fminf(s_yy[buf][warp_n + lane], s_yy[buf][warp_n + 32 + lane]);
            #pragma unroll
            for (int o = 16; o > 0; o >>= 1) ymin = fminf(ymin, __shfl_xor_sync(0xffffffffu, ymin, o));

            const float qmin  = xmin + ymin;   // q = xx+yy >= 0
            // lb_min >= (1-3/16)*qmin - 2*cmax - 0.25  (e4m3 error bound)
            const float lbmin = fmaf(-0.1875f, qmin, fmaf(-2.f, cmax, qmin)) - 0.25f;

            if (force || lbmin < sCut) {   // rare: per-element check + exact fp32 recompute
                float yv[16];
                #pragma unroll
                for (int k2 = 0; k2 < 16; k2++)
                    yv[k2] = s_yy[buf][warp_n + (k2 >> 1) * 8 + 2 * (lane & 3) + (k2 & 1)];
                const int n0 = ((i + tl) & 63) * TN;
                #pragma unroll 1
                for (int mf = 0; mf < 2; mf++)
                    for (int nf = 0; nf < 8; nf++)
                        for (int e = 0; e < 4; e++) {
                            const float q  = xv[mf * 2 + (e >> 1)] + yv[nf * 2 + (e & 1)];
                            const float s  = fmaf(-2.f, acc[mf][nf][e], q);
                            const float lb = fmaf(-0.1875f, q, s) - 0.25f;
                            if (force || lb < sCut) {
                                const int rg = row0 + warp_m + mf * 16 + (lane >> 2) + 8 * (e >> 1);
                                const int cg = n0 + warp_n + nf * 8 + 2 * (lane & 3) + (e & 1);
                                const float* xr = Xtest  + (size_t)rg * DIM;
                                const float* yr = Xtrain + (size_t)cg * DIM;
                                float cr = 0.f;
                                #pragma unroll 8
                                for (int d = 0; d < DIM; d++) cr = fmaf(xr[d], yr[d], cr);
                                const float se = fmaxf(fmaf(-2.f, cr, g_XX[rg] + g_YY[cg]), 0.f);
                                const float ev = expf(se * negInv);
                                if (ev != 0.f)
                                    atomicAdd(&out[rg], sv * ev * s_mu[buf][warp_n + nf * 8 + 2 * (lane & 3) + (e & 1)]);
                            }
                        }
            }
            __syncthreads();   // epilogue done before buffers are overwritten
        }
        i = seg_end;
    }
}

// ============================================================================
// kernel_launch: inputs in metadata order:
//   0 Xtest, 1 Xtrain, 2 mu, 3 mean_const, 4 lengthscale, 5 signal_var
// ============================================================================
extern "C" void kernel_launch(void* const* d_in, const int* in_sizes, int n_in,
                              void* d_out, int out_size)
{
    const float* Xtest      = (const float*)d_in[0];
    const float* Xtrain     = (const float*)d_in[1];
    const float* mu         = (const float*)d_in[2];
    const float* mean_const = (const float*)d_in[3];
    const float* lengthsc   = (const float*)d_in[4];
    const float* signal_var = (const float*)d_in[5];
    float* out = (float*)d_out;

    const int DYN = 3 * 32768 + 1024;   // A + B0 + B1 + align slack (97KB -> 2 CTAs/SM)
    cudaFuncSetAttribute(gp_hmma_kernel, cudaFuncAttributeMaxDynamicSharedMemorySize, DYN);

    gp_precompute_kernel<<<(NTEST + NTRAIN) / 8, 256>>>(Xtest, Xtrain, mean_const, out);
    gp_hmma_kernel<<<GRID, 256, DYN>>>(Xtest, Xtrain, mu, lengthsc, signal_var, out);
}